// round 2
// baseline (speedup 1.0000x reference)
#include <cuda_runtime.h>
#include <float.h>

// ROI max pooling via separable 4x4 max pyramid.
// feat: [B=8, H=50, W=50, C=256] fp32 NHWC; rois: [N,5] (img,x1,y1,x2,y2) incl.
// All dataset ROIs are 28x28 with 7x7 pooling -> each bin is an aligned 4x4
// window: out[roi,br,bc] = max feat[img, y1+4br..+3, x1+4bc..+3].
// Pass A: Hm[b,y,x] = max_x..x+3 feat   (x: 0..46)
// Pass B: Vm[b,y,x] = max_y..y+3 Hm     (y: 0..46)
// Pass C: out bin = Vm[img, y1+4br, x1+4bc]  (single float4 load/thread)
// General fallback (non-28x28 ROI or pool!=7): direct loop over feat.

#define FH 50
#define FW 50
#define CCH 256
#define PH 7
#define PW 7
#define HX 47              // FW - 3
#define HY 47              // FH - 3
#define NCHUNK 6           // ceil(47/8)

__device__ float g_hm[8 * FH * HX * CCH];   // 19.3 MB
__device__ float g_vm[8 * HY * HX * CCH];   // 18.1 MB

__device__ __forceinline__ float4 vmax4(float4 a, float4 b, float4 c, float4 d) {
    float4 r;
    r.x = fmaxf(fmaxf(a.x, b.x), fmaxf(c.x, d.x));
    r.y = fmaxf(fmaxf(a.y, b.y), fmaxf(c.y, d.y));
    r.z = fmaxf(fmaxf(a.z, b.z), fmaxf(c.z, d.z));
    r.w = fmaxf(fmaxf(a.w, b.w), fmaxf(c.w, d.w));
    return r;
}

// Pass A: horizontal window-4 max. One CTA = (b, y, x-chunk of 8 outputs).
__global__ __launch_bounds__(64)
void hmax_kernel(const float* __restrict__ feat)
{
    const int id    = blockIdx.x;          // (b*FH + y)*NCHUNK + chunk
    const int chunk = id % NCHUNK;
    const int by    = id / NCHUNK;         // b*FH + y
    const int x0    = chunk * 8;
    const int coff  = threadIdx.x * 4;

    const float* rowp = feat + (size_t)by * (FW * CCH) + coff;
    float*       outp = g_hm + (size_t)by * (HX * CCH) + coff;

    float4 v[11];
    #pragma unroll
    for (int j = 0; j < 11; ++j) {
        const int x = x0 + j;
        v[j] = (x < FW) ? *reinterpret_cast<const float4*>(rowp + (size_t)x * CCH)
                        : make_float4(-FLT_MAX, -FLT_MAX, -FLT_MAX, -FLT_MAX);
    }
    #pragma unroll
    for (int i = 0; i < 8; ++i) {
        const int xo = x0 + i;
        if (xo < HX) {
            *reinterpret_cast<float4*>(outp + (size_t)xo * CCH) =
                vmax4(v[i], v[i + 1], v[i + 2], v[i + 3]);
        }
    }
}

// Pass B: vertical window-4 max over Hm. One CTA = (b, x, y-chunk of 8).
__global__ __launch_bounds__(64)
void vmax_kernel()
{
    const int id    = blockIdx.x;          // (b*HX + x)*NCHUNK + chunk
    const int chunk = id % NCHUNK;
    const int bx    = id / NCHUNK;
    const int b     = bx / HX;
    const int x     = bx - b * HX;
    const int y0    = chunk * 8;
    const int coff  = threadIdx.x * 4;

    const float* inp  = g_hm + (((size_t)b * FH) * HX + x) * CCH + coff;
    float*       outp = g_vm + (((size_t)b * HY) * HX + x) * CCH + coff;

    float4 v[11];
    #pragma unroll
    for (int j = 0; j < 11; ++j) {
        const int y = y0 + j;
        v[j] = (y < FH) ? *reinterpret_cast<const float4*>(inp + (size_t)y * (HX * CCH))
                        : make_float4(-FLT_MAX, -FLT_MAX, -FLT_MAX, -FLT_MAX);
    }
    #pragma unroll
    for (int i = 0; i < 8; ++i) {
        const int yo = y0 + i;
        if (yo < HY) {
            *reinterpret_cast<float4*>(outp + (size_t)yo * (HX * CCH)) =
                vmax4(v[i], v[i + 1], v[i + 2], v[i + 3]);
        }
    }
}

// Pass C: gather. One CTA per (roi, bin). Fast path: single lookup into Vm.
__global__ __launch_bounds__(64)
void gather_kernel(const float* __restrict__ feat,
                   const int*   __restrict__ rois,
                   float*       __restrict__ out)
{
    const int bin = blockIdx.x;            // roi*49 + br*7 + bc
    const int roi = bin / (PH * PW);
    const int rem = bin - roi * (PH * PW);
    const int br  = rem / PW;
    const int bc  = rem - br * PW;

    const int* r = rois + roi * 5;
    const int img = r[0];
    const int x1  = r[1];
    const int y1  = r[2];
    const int x2  = r[3];
    const int y2  = r[4];
    const int roi_h = y2 - y1 + 1;
    const int roi_w = x2 - x1 + 1;

    const int coff = threadIdx.x * 4;
    float4 m;

    if (roi_h == 28 && roi_w == 28) {
        const int yy = y1 + 4 * br;
        const int xx = x1 + 4 * bc;
        m = *reinterpret_cast<const float4*>(
            g_vm + (((size_t)img * HY + yy) * HX + xx) * CCH + coff);
    } else {
        // General fallback: direct max over the bin's pixel range.
        const int rs = (br * roi_h + PH - 1) / PH;
        const int re = (br == PH - 1) ? roi_h : ((br + 1) * roi_h + PH - 1) / PH;
        const int cs = (bc * roi_w + PW - 1) / PW;
        const int ce = (bc == PW - 1) ? roi_w : ((bc + 1) * roi_w + PW - 1) / PW;
        const float* base = feat
            + (((size_t)img * FH + (size_t)y1) * FW + (size_t)x1) * CCH + coff;
        m = make_float4(-FLT_MAX, -FLT_MAX, -FLT_MAX, -FLT_MAX);
        for (int y = rs; y < re; ++y) {
            const float* rowp = base + (size_t)y * (FW * CCH);
            for (int x = cs; x < ce; ++x) {
                const float4 v = *reinterpret_cast<const float4*>(rowp + (size_t)x * CCH);
                m.x = fmaxf(m.x, v.x); m.y = fmaxf(m.y, v.y);
                m.z = fmaxf(m.z, v.z); m.w = fmaxf(m.w, v.w);
            }
        }
    }

    *reinterpret_cast<float4*>(out + (size_t)bin * CCH + coff) = m;
}

extern "C" void kernel_launch(void* const* d_in, const int* in_sizes, int n_in,
                              void* d_out, int out_size)
{
    const float* feat = (const float*)d_in[0];
    const int*   rois = (const int*)d_in[1];
    const int n_rois = in_sizes[1] / 5;
    float* out = (float*)d_out;

    hmax_kernel<<<8 * FH * NCHUNK, 64>>>(feat);
    vmax_kernel<<<8 * HX * NCHUNK, 64>>>();
    gather_kernel<<<n_rois * PH * PW, 64>>>(feat, rois, out);
}

// round 3
// speedup vs baseline: 1.2239x; 1.2239x over previous
#include <cuda_runtime.h>
#include <float.h>

// ROI max pooling, 2-pass.
// feat: [B=8, H=50, W=50, C=256] fp32 NHWC; rois: [N,5] (img,x1,y1,x2,y2) incl.
// Dataset ROIs are 28x28 with 7x7 pooling -> each bin = aligned 4x4 window:
//   out[roi,br,bc] = max feat[img, y1+4br..+3, x1+4bc..+3].
// Pass A: Hm[b,y,x] = max_{x..x+3} feat[b,y,x']   (x: 0..46)
// Pass B: out bin = max_{j=0..3} Hm[img, y1+4br+j, x1+4bc]  (4 float4 loads)
// General fallback (non-28x28 ROI): direct loop over feat.

#define FH 50
#define FW 50
#define CCH 256
#define PH 7
#define PW 7
#define HX 47               // FW - 3
#define OUTS_PER_CTA 4
#define NCHUNK 12           // ceil(47/4)

__device__ float g_hm[8 * FH * HX * CCH];   // 19.3 MB

__device__ __forceinline__ float4 vmax2(float4 a, float4 b) {
    float4 r;
    r.x = fmaxf(a.x, b.x);
    r.y = fmaxf(a.y, b.y);
    r.z = fmaxf(a.z, b.z);
    r.w = fmaxf(a.w, b.w);
    return r;
}

// Pass A: horizontal window-4 max. One CTA = (b, y, chunk of 4 outputs).
// 7 live float4 loads -> no spills at 64 regs.
__global__ __launch_bounds__(64)
void hmax_kernel(const float* __restrict__ feat)
{
    const int id    = blockIdx.x;           // (b*FH + y)*NCHUNK + chunk
    const int chunk = id % NCHUNK;
    const int by    = id / NCHUNK;          // b*FH + y
    const int x0    = chunk * OUTS_PER_CTA;
    const int coff  = threadIdx.x * 4;

    const float* rowp = feat + (size_t)by * (FW * CCH) + coff;
    float*       outp = g_hm + (size_t)by * (HX * CCH) + coff;

    float4 v[7];
    #pragma unroll
    for (int j = 0; j < 7; ++j) {
        const int x = x0 + j;
        v[j] = (x < FW) ? *reinterpret_cast<const float4*>(rowp + (size_t)x * CCH)
                        : make_float4(-FLT_MAX, -FLT_MAX, -FLT_MAX, -FLT_MAX);
    }

    // pairwise maxes reduce live registers quickly
    float4 m01 = vmax2(v[0], v[1]);
    float4 m12 = vmax2(v[1], v[2]);
    float4 m23 = vmax2(v[2], v[3]);
    float4 m34 = vmax2(v[3], v[4]);
    float4 m45 = vmax2(v[4], v[5]);
    float4 m56 = vmax2(v[5], v[6]);

    float4 o[4];
    o[0] = vmax2(m01, m23);
    o[1] = vmax2(m12, m34);
    o[2] = vmax2(m23, m45);
    o[3] = vmax2(m34, m56);

    #pragma unroll
    for (int i = 0; i < 4; ++i) {
        const int xo = x0 + i;
        if (xo < HX)
            *reinterpret_cast<float4*>(outp + (size_t)xo * CCH) = o[i];
    }
}

// Pass B: gather. One CTA per (roi, bin). Fast path: 4 loads from Hm.
__global__ __launch_bounds__(64)
void gather_kernel(const float* __restrict__ feat,
                   const int*   __restrict__ rois,
                   float*       __restrict__ out)
{
    const int bin = blockIdx.x;             // roi*49 + br*7 + bc
    const int roi = bin / (PH * PW);
    const int rem = bin - roi * (PH * PW);
    const int br  = rem / PW;
    const int bc  = rem - br * PW;

    const int* r = rois + roi * 5;
    const int img = r[0];
    const int x1  = r[1];
    const int y1  = r[2];
    const int x2  = r[3];
    const int y2  = r[4];
    const int roi_h = y2 - y1 + 1;
    const int roi_w = x2 - x1 + 1;

    const int coff = threadIdx.x * 4;
    float4 m;

    if (roi_h == 28 && roi_w == 28) {
        const int yy = y1 + 4 * br;
        const int xx = x1 + 4 * bc;
        const float* p = g_hm + (((size_t)img * FH + yy) * HX + xx) * CCH + coff;
        const size_t rstride = (size_t)HX * CCH;
        const float4 a = *reinterpret_cast<const float4*>(p);
        const float4 b = *reinterpret_cast<const float4*>(p + rstride);
        const float4 c = *reinterpret_cast<const float4*>(p + 2 * rstride);
        const float4 d = *reinterpret_cast<const float4*>(p + 3 * rstride);
        m = vmax2(vmax2(a, b), vmax2(c, d));
    } else {
        // General fallback: direct max over the bin's pixel range in feat.
        const int rs = (br * roi_h + PH - 1) / PH;
        const int re = (br == PH - 1) ? roi_h : ((br + 1) * roi_h + PH - 1) / PH;
        const int cs = (bc * roi_w + PW - 1) / PW;
        const int ce = (bc == PW - 1) ? roi_w : ((bc + 1) * roi_w + PW - 1) / PW;
        const float* base = feat
            + (((size_t)img * FH + (size_t)y1) * FW + (size_t)x1) * CCH + coff;
        m = make_float4(-FLT_MAX, -FLT_MAX, -FLT_MAX, -FLT_MAX);
        for (int y = rs; y < re; ++y) {
            const float* rowp = base + (size_t)y * (FW * CCH);
            for (int x = cs; x < ce; ++x) {
                const float4 v = *reinterpret_cast<const float4*>(rowp + (size_t)x * CCH);
                m.x = fmaxf(m.x, v.x); m.y = fmaxf(m.y, v.y);
                m.z = fmaxf(m.z, v.z); m.w = fmaxf(m.w, v.w);
            }
        }
    }

    *reinterpret_cast<float4*>(out + (size_t)bin * CCH + coff) = m;
}

extern "C" void kernel_launch(void* const* d_in, const int* in_sizes, int n_in,
                              void* d_out, int out_size)
{
    const float* feat = (const float*)d_in[0];
    const int*   rois = (const int*)d_in[1];
    const int n_rois = in_sizes[1] / 5;
    float* out = (float*)d_out;

    hmax_kernel<<<8 * FH * NCHUNK, 64>>>(feat);
    gather_kernel<<<n_rois * PH * PW, 64>>>(feat, rois, out);
}

// round 4
// speedup vs baseline: 1.4199x; 1.1602x over previous
#include <cuda_runtime.h>
#include <float.h>

// ROI max pooling, 2-pass.
// feat: [B=8, H=50, W=50, C=256] fp32 NHWC; rois: [N,5] (img,x1,y1,x2,y2) incl.
// Dataset ROIs are 28x28 with 7x7 pooling -> each bin = aligned 4x4 window:
//   out[roi,br,bc] = max feat[img, y1+4br..+3, x1+4bc..+3].
// Pass A: Hm[b,y,x] = max_{x..x+3} feat[b,y,x']   (x: 0..46)
// Pass B: one CTA per (roi, bin-row): 7 bins, 4 Hm-row loads each.
// General fallback (non-28x28 ROI): direct loop over feat.

#define FH 50
#define FW 50
#define CCH 256
#define PH 7
#define PW 7
#define HX 47               // FW - 3
#define NCHUNK 12           // ceil(47/4), hmax chunks of 4 outputs

__device__ float g_hm[8 * FH * HX * CCH];   // 19.3 MB

__device__ __forceinline__ float4 vmax2(float4 a, float4 b) {
    float4 r;
    r.x = fmaxf(a.x, b.x);
    r.y = fmaxf(a.y, b.y);
    r.z = fmaxf(a.z, b.z);
    r.w = fmaxf(a.w, b.w);
    return r;
}

// Pass A: horizontal window-4 max. One CTA = (b, y, chunk of 4 outputs).
__global__ __launch_bounds__(64)
void hmax_kernel(const float* __restrict__ feat)
{
    const int id    = blockIdx.x;           // (b*FH + y)*NCHUNK + chunk
    const int chunk = id % NCHUNK;
    const int by    = id / NCHUNK;          // b*FH + y
    const int x0    = chunk * 4;
    const int coff  = threadIdx.x * 4;

    const float* rowp = feat + (size_t)by * (FW * CCH) + coff;
    float*       outp = g_hm + (size_t)by * (HX * CCH) + coff;

    float4 v[7];
    #pragma unroll
    for (int j = 0; j < 7; ++j) {
        const int x = x0 + j;
        v[j] = (x < FW) ? *reinterpret_cast<const float4*>(rowp + (size_t)x * CCH)
                        : make_float4(-FLT_MAX, -FLT_MAX, -FLT_MAX, -FLT_MAX);
    }

    float4 m01 = vmax2(v[0], v[1]);
    float4 m12 = vmax2(v[1], v[2]);
    float4 m23 = vmax2(v[2], v[3]);
    float4 m34 = vmax2(v[3], v[4]);
    float4 m45 = vmax2(v[4], v[5]);
    float4 m56 = vmax2(v[5], v[6]);

    float4 o0 = vmax2(m01, m23);
    float4 o1 = vmax2(m12, m34);
    float4 o2 = vmax2(m23, m45);
    float4 o3 = vmax2(m34, m56);

    if (x0 + 0 < HX) *reinterpret_cast<float4*>(outp + (size_t)(x0 + 0) * CCH) = o0;
    if (x0 + 1 < HX) *reinterpret_cast<float4*>(outp + (size_t)(x0 + 1) * CCH) = o1;
    if (x0 + 2 < HX) *reinterpret_cast<float4*>(outp + (size_t)(x0 + 2) * CCH) = o2;
    if (x0 + 3 < HX) *reinterpret_cast<float4*>(outp + (size_t)(x0 + 3) * CCH) = o3;
}

// Pass B: one CTA per (roi, bin-row). Each thread owns 4 channels and
// produces all 7 bins of the row: 4 Hm-rows x 7 bins = 28 loads, MLP 7.
__global__ __launch_bounds__(64)
void gather_kernel(const float* __restrict__ feat,
                   const int*   __restrict__ rois,
                   float*       __restrict__ out)
{
    const int roi = blockIdx.x / PH;
    const int br  = blockIdx.x - roi * PH;

    const int* r = rois + roi * 5;
    const int img = r[0];
    const int x1  = r[1];
    const int y1  = r[2];
    const int x2  = r[3];
    const int y2  = r[4];
    const int roi_h = y2 - y1 + 1;
    const int roi_w = x2 - x1 + 1;

    const int coff = threadIdx.x * 4;
    float4 acc[PW];

    if (roi_h == 28 && roi_w == 28) {
        const int yy = y1 + 4 * br;
        const float* base = g_hm
            + (((size_t)img * FH + yy) * HX + x1) * CCH + coff;
        const size_t rstride = (size_t)HX * CCH;

        #pragma unroll
        for (int j = 0; j < 4; ++j) {
            const float* p = base + j * rstride;
            float4 t[PW];
            #pragma unroll
            for (int bc = 0; bc < PW; ++bc)
                t[bc] = *reinterpret_cast<const float4*>(p + (size_t)(4 * bc) * CCH);
            #pragma unroll
            for (int bc = 0; bc < PW; ++bc)
                acc[bc] = (j == 0) ? t[bc] : vmax2(acc[bc], t[bc]);
        }
    } else {
        // General fallback: direct max over each bin's pixel range in feat.
        const int rs = (br * roi_h + PH - 1) / PH;
        const int re = (br == PH - 1) ? roi_h : ((br + 1) * roi_h + PH - 1) / PH;
        const float* base = feat
            + (((size_t)img * FH + (size_t)y1) * FW + (size_t)x1) * CCH + coff;
        #pragma unroll
        for (int bc = 0; bc < PW; ++bc) {
            const int cs = (bc * roi_w + PW - 1) / PW;
            const int ce = (bc == PW - 1) ? roi_w : ((bc + 1) * roi_w + PW - 1) / PW;
            float4 m = make_float4(-FLT_MAX, -FLT_MAX, -FLT_MAX, -FLT_MAX);
            for (int y = rs; y < re; ++y) {
                const float* rowp = base + (size_t)y * (FW * CCH);
                for (int x = cs; x < ce; ++x) {
                    const float4 v = *reinterpret_cast<const float4*>(rowp + (size_t)x * CCH);
                    m.x = fmaxf(m.x, v.x); m.y = fmaxf(m.y, v.y);
                    m.z = fmaxf(m.z, v.z); m.w = fmaxf(m.w, v.w);
                }
            }
            acc[bc] = m;
        }
    }

    float* obase = out + ((size_t)(roi * PH + br) * PW) * CCH + coff;
    #pragma unroll
    for (int bc = 0; bc < PW; ++bc)
        *reinterpret_cast<float4*>(obase + (size_t)bc * CCH) = acc[bc];
}

extern "C" void kernel_launch(void* const* d_in, const int* in_sizes, int n_in,
                              void* d_out, int out_size)
{
    const float* feat = (const float*)d_in[0];
    const int*   rois = (const int*)d_in[1];
    const int n_rois = in_sizes[1] / 5;
    float* out = (float*)d_out;

    hmax_kernel<<<8 * FH * NCHUNK, 64>>>(feat);
    gather_kernel<<<n_rois * PH, 64>>>(feat, rois, out);
}